// round 7
// baseline (speedup 1.0000x reference)
#include <cuda_runtime.h>
#include <math.h>

#define D_MODEL 768
#define NHEAD 12
#define HDIM 64
#define DQKV 2304
#define DFF 3072
#define TOTAL_MAX 8192
#define SMAX 1024

// ---------------- scratch (static device globals: allocation-free) ----------
__device__ float g_ln1 [TOTAL_MAX * D_MODEL];
__device__ float g_qkv [TOTAL_MAX * DQKV];
__device__ float g_attn[TOTAL_MAX * D_MODEL];
__device__ float g_ln2 [TOTAL_MAX * D_MODEL];
__device__ float g_mff [TOTAL_MAX * DFF];

// ---------------- LayerNorm: one block per row, 256 threads -----------------
__global__ __launch_bounds__(256) void ln_kernel(
    const float* __restrict__ x, const float* __restrict__ g,
    const float* __restrict__ beta, float* __restrict__ out)
{
    int row = blockIdx.x;
    const float* xr = x + (size_t)row * D_MODEL;
    float v[3];
    float s = 0.f;
#pragma unroll
    for (int i = 0; i < 3; i++) { v[i] = xr[threadIdx.x + i * 256]; s += v[i]; }

    __shared__ float red[8];
    __shared__ float stat[2];
#pragma unroll
    for (int o = 16; o; o >>= 1) s += __shfl_xor_sync(0xffffffffu, s, o);
    if ((threadIdx.x & 31) == 0) red[threadIdx.x >> 5] = s;
    __syncthreads();
    if (threadIdx.x < 8) {
        s = red[threadIdx.x];
#pragma unroll
        for (int o = 4; o; o >>= 1) s += __shfl_xor_sync(0xffu, s, o);
        if (threadIdx.x == 0) stat[0] = s * (1.f / (float)D_MODEL);
    }
    __syncthreads();
    float mu = stat[0];
    float s2 = 0.f;
#pragma unroll
    for (int i = 0; i < 3; i++) { float d0 = v[i] - mu; s2 += d0 * d0; }
#pragma unroll
    for (int o = 16; o; o >>= 1) s2 += __shfl_xor_sync(0xffffffffu, s2, o);
    __syncthreads();           // red reuse is safe: prior reads happened before this point
    if ((threadIdx.x & 31) == 0) red[threadIdx.x >> 5] = s2;
    __syncthreads();
    if (threadIdx.x < 8) {
        s2 = red[threadIdx.x];
#pragma unroll
        for (int o = 4; o; o >>= 1) s2 += __shfl_xor_sync(0xffu, s2, o);
        if (threadIdx.x == 0) stat[1] = rsqrtf(s2 * (1.f / (float)D_MODEL) + 1e-6f);
    }
    __syncthreads();
    float rstd = stat[1];
#pragma unroll
    for (int i = 0; i < 3; i++) {
        int col = threadIdx.x + i * 256;
        out[(size_t)row * D_MODEL + col] = (v[i] - mu) * rstd * g[col] + beta[col];
    }
}

// ---------------- SGEMM: C = A[MxK] * B[KxN] + bias, optional epilogues -----
// BM=BN=128, BK=8, 256 threads, 8x8 register tile.
// EPI: 0 = bias only, 1 = bias + residual, 2 = bias + exact GELU
template <int EPI>
__global__ __launch_bounds__(256) void sgemm_kernel(
    const float* __restrict__ A, const float* __restrict__ B,
    const float* __restrict__ bias, const float* __restrict__ resid,
    float* __restrict__ C, int M, int N, int K)
{
    __shared__ float As[8][128];
    __shared__ float Bs[8][128];

    int bm = blockIdx.y * 128, bn = blockIdx.x * 128;
    int t = threadIdx.x;
    int tx = t & 15, ty = t >> 4;

    float acc[8][8];
#pragma unroll
    for (int i = 0; i < 8; i++)
#pragma unroll
        for (int j = 0; j < 8; j++) acc[i][j] = 0.f;

    int arow = t >> 1, acol = (t & 1) * 4;
    int brow = t >> 5, bcol = (t & 31) * 4;
    const float* Aptr = A + (size_t)(bm + arow) * K + acol;
    const float* Bptr = B + (size_t)brow * N + bn + bcol;
    bool aval = (bm + arow) < M;

    for (int k0 = 0; k0 < K; k0 += 8) {
        float4 av = aval ? *(const float4*)Aptr : make_float4(0.f, 0.f, 0.f, 0.f);
        float4 bv = *(const float4*)Bptr;
        Aptr += 8;
        Bptr += (size_t)8 * N;

        As[acol + 0][arow] = av.x;
        As[acol + 1][arow] = av.y;
        As[acol + 2][arow] = av.z;
        As[acol + 3][arow] = av.w;
        *(float4*)&Bs[brow][bcol] = bv;
        __syncthreads();

#pragma unroll
        for (int k = 0; k < 8; k++) {
            float4 a0 = *(const float4*)&As[k][ty * 8];
            float4 a1 = *(const float4*)&As[k][ty * 8 + 4];
            float4 b0 = *(const float4*)&Bs[k][tx * 8];
            float4 b1 = *(const float4*)&Bs[k][tx * 8 + 4];
            float ar[8] = {a0.x, a0.y, a0.z, a0.w, a1.x, a1.y, a1.z, a1.w};
            float br[8] = {b0.x, b0.y, b0.z, b0.w, b1.x, b1.y, b1.z, b1.w};
#pragma unroll
            for (int i = 0; i < 8; i++)
#pragma unroll
                for (int j = 0; j < 8; j++) acc[i][j] += ar[i] * br[j];
        }
        __syncthreads();
    }

#pragma unroll
    for (int i = 0; i < 8; i++) {
        int row = bm + ty * 8 + i;
        if (row >= M) continue;
#pragma unroll
        for (int j = 0; j < 8; j++) {
            int col = bn + tx * 8 + j;
            float v = acc[i][j] + bias[col];
            if (EPI == 1) v += resid[(size_t)row * N + col];
            if (EPI == 2) v = 0.5f * v * (1.f + erff(v * 0.70710678118654752f));
            C[(size_t)row * N + col] = v;
        }
    }
}

// ---------------- Ragged flash attention (fp32, 32-query tiles) -------------
// grid: (SMAX/32, NHEAD, B). block: 128 threads.
__global__ __launch_bounds__(128) void attn_kernel(
    const float* __restrict__ qkv, const int* __restrict__ cu,
    float* __restrict__ out)
{
    int b = blockIdx.z, h = blockIdx.y, qt = blockIdx.x;
    int s0 = cu[b], s1 = cu[b + 1];
    int len = s1 - s0;
    int q0 = qt * 32;
    if (q0 >= len) return;
    int nq = min(32, len - q0);

    __shared__ float Qs[32][65];
    __shared__ float Ks[32][65];
    __shared__ float Vs[32][65];
    __shared__ float Ss[32][33];
    __shared__ float corr_s[32], ls_s[32];

    int t = threadIdx.x;
    int qi = t & 31;          // score row & O row owned by this thread
    int kwarp = t >> 5;       // 0..3
    int oc = kwarp * 16;      // O column base

    // load Q tile (zero-fill invalid rows)
    {
        int r = t >> 2, cbase = (t & 3) * 16;
        const float* qp = qkv + (size_t)(s0 + q0 + r) * DQKV + h * HDIM;
#pragma unroll
        for (int i = 0; i < 16; i++)
            Qs[r][cbase + i] = (r < nq) ? qp[cbase + i] : 0.f;
    }

    const float scale = 0.125f;  // 1/sqrt(64)
    float m = -1e30f, l = 0.f;   // meaningful on threads t<32 (row t)
    float O[16];
#pragma unroll
    for (int i = 0; i < 16; i++) O[i] = 0.f;

    for (int k0 = 0; k0 < len; k0 += 32) {
        int nk = min(32, len - k0);
        // load K/V tiles
        {
            int r = t >> 2, cbase = (t & 3) * 16;
            const float* kp = qkv + (size_t)(s0 + k0 + r) * DQKV + h * HDIM + D_MODEL;
            if (r < nk) {
#pragma unroll
                for (int i = 0; i < 16; i++) {
                    Ks[r][cbase + i] = kp[cbase + i];
                    Vs[r][cbase + i] = kp[D_MODEL + cbase + i];
                }
            } else {
#pragma unroll
                for (int i = 0; i < 16; i++) {
                    Ks[r][cbase + i] = 0.f;
                    Vs[r][cbase + i] = 0.f;
                }
            }
        }
        __syncthreads();

        // scores: this thread computes row qi, cols [kwarp*8, kwarp*8+8)
        float sreg[8];
#pragma unroll
        for (int c = 0; c < 8; c++) sreg[c] = 0.f;
#pragma unroll 16
        for (int d = 0; d < 64; d++) {
            float rq = Qs[qi][d];
#pragma unroll
            for (int c = 0; c < 8; c++)
                sreg[c] += rq * Ks[kwarp * 8 + c][d];
        }
#pragma unroll
        for (int c = 0; c < 8; c++) {
            int kj = kwarp * 8 + c;
            Ss[qi][kj] = (kj < nk) ? sreg[c] * scale : -1e30f;
        }
        __syncthreads();

        // online softmax bookkeeping (one warp: thread t handles row t)
        if (t < 32) {
            float tm = m;
#pragma unroll
            for (int j = 0; j < 32; j++) tm = fmaxf(tm, Ss[t][j]);
            float corr = __expf(m - tm);
            float ssum = 0.f;
#pragma unroll
            for (int j = 0; j < 32; j++) {
                float p = __expf(Ss[t][j] - tm);
                Ss[t][j] = p;
                ssum += p;
            }
            l = l * corr + ssum;
            m = tm;
            corr_s[t] = corr;
        }
        __syncthreads();

        // O update: O[qi][oc..oc+15]
        float corr = corr_s[qi];
#pragma unroll
        for (int i = 0; i < 16; i++) O[i] *= corr;
        for (int j = 0; j < nk; j++) {
            float p = Ss[qi][j];
#pragma unroll
            for (int i = 0; i < 16; i++)
                O[i] += p * Vs[j][oc + i];
        }
        __syncthreads();
    }

    if (t < 32) ls_s[t] = l;
    __syncthreads();
    float inv = 1.f / ls_s[qi];
    if (qi < nq) {
        float* op = out + (size_t)(s0 + q0 + qi) * D_MODEL + h * HDIM + oc;
#pragma unroll
        for (int i = 0; i < 16; i++) op[i] = O[i] * inv;
    }
}

// ---------------- launch --------------------------------------------------
extern "C" void kernel_launch(void* const* d_in, const int* in_sizes, int n_in,
                              void* d_out, int out_size)
{
    const float* x    = (const float*)d_in[0];
    const int*   cu   = (const int*)  d_in[1];
    const float* g1   = (const float*)d_in[2];
    const float* be1  = (const float*)d_in[3];
    const float* Wqkv = (const float*)d_in[4];
    const float* bqkv = (const float*)d_in[5];
    const float* Wo   = (const float*)d_in[6];
    const float* bo   = (const float*)d_in[7];
    const float* g2   = (const float*)d_in[8];
    const float* be2  = (const float*)d_in[9];
    const float* W1   = (const float*)d_in[10];
    const float* bf1  = (const float*)d_in[11];
    const float* W2   = (const float*)d_in[12];
    const float* bf2  = (const float*)d_in[13];
    float* out = (float*)d_out;

    int total = in_sizes[0] / D_MODEL;
    int nb    = in_sizes[1] - 1;

    float *ln1, *qkvb, *attnb, *ln2, *mff;
    cudaGetSymbolAddress((void**)&ln1,   g_ln1);
    cudaGetSymbolAddress((void**)&qkvb,  g_qkv);
    cudaGetSymbolAddress((void**)&attnb, g_attn);
    cudaGetSymbolAddress((void**)&ln2,   g_ln2);
    cudaGetSymbolAddress((void**)&mff,   g_mff);

    int mblk = (total + 127) / 128;

    // 1. LN1
    ln_kernel<<<total, 256>>>(x, g1, be1, ln1);
    // 2. QKV = LN1 @ Wqkv + bqkv
    sgemm_kernel<0><<<dim3(DQKV / 128, mblk), 256>>>(ln1, Wqkv, bqkv, nullptr,
                                                     qkvb, total, DQKV, D_MODEL);
    // 3. ragged attention
    attn_kernel<<<dim3(SMAX / 32, NHEAD, nb), 128>>>(qkvb, cu, attnb);
    // 4. out = x + attn @ Wo + bo
    sgemm_kernel<1><<<dim3(D_MODEL / 128, mblk), 256>>>(attnb, Wo, bo, x,
                                                        out, total, D_MODEL, D_MODEL);
    // 5. LN2
    ln_kernel<<<total, 256>>>(out, g2, be2, ln2);
    // 6. m = gelu(LN2 @ W1 + b_fc1)
    sgemm_kernel<2><<<dim3(DFF / 128, mblk), 256>>>(ln2, W1, bf1, nullptr,
                                                    mff, total, DFF, D_MODEL);
    // 7. out = out + m @ W2 + b_fc2
    sgemm_kernel<1><<<dim3(D_MODEL / 128, mblk), 256>>>(mff, W2, bf2, out,
                                                        out, total, D_MODEL, DFF);
}

// round 9
// speedup vs baseline: 2.7023x; 2.7023x over previous
#include <cuda_runtime.h>
#include <cuda_bf16.h>
#include <math.h>
#include <stdint.h>

#define D_MODEL 768
#define NHEAD 12
#define HDIM 64
#define DQKV 2304
#define DFF 3072
#define TOTAL_MAX 8192
#define SMAX 1024

// ======================= PTX helpers (sm_80-compatible only) ================
__device__ __forceinline__ uint32_t smem_to_u32(const void* p) {
    uint32_t a;
    asm("{ .reg .u64 t; cvta.to.shared.u64 t, %1; cvt.u32.u64 %0, t; }"
        : "=r"(a) : "l"(p));
    return a;
}

__device__ __forceinline__ void cp_async16(uint32_t dst, const void* src, uint32_t sz) {
    asm volatile("cp.async.cg.shared.global [%0], [%1], 16, %2;"
                 :: "r"(dst), "l"(src), "r"(sz) : "memory");
}
#define CP_COMMIT()  asm volatile("cp.async.commit_group;" ::: "memory")
#define CP_WAIT(N)   asm volatile("cp.async.wait_group %0;" :: "n"(N) : "memory")

__device__ __forceinline__ void ldsm4(uint32_t* r, uint32_t addr) {
    asm volatile("ldmatrix.sync.aligned.m8n8.x4.shared.b16 {%0,%1,%2,%3}, [%4];"
                 : "=r"(r[0]), "=r"(r[1]), "=r"(r[2]), "=r"(r[3]) : "r"(addr));
}

__device__ __forceinline__ void mma16816(float* d, const uint32_t* a, const uint32_t* b) {
    asm volatile(
        "mma.sync.aligned.m16n8k16.row.col.f32.bf16.bf16.f32 "
        "{%0,%1,%2,%3}, {%4,%5,%6,%7}, {%8,%9}, {%0,%1,%2,%3};"
        : "+f"(d[0]), "+f"(d[1]), "+f"(d[2]), "+f"(d[3])
        : "r"(a[0]), "r"(a[1]), "r"(a[2]), "r"(a[3]), "r"(b[0]), "r"(b[1]));
}

// ======================= scratch (device globals) ===========================
__device__ float          g_qkv [TOTAL_MAX * DQKV];
__device__ __nv_bfloat16  g_ln1h[TOTAL_MAX * D_MODEL], g_ln1l[TOTAL_MAX * D_MODEL];
__device__ __nv_bfloat16  g_atth[TOTAL_MAX * D_MODEL], g_attl[TOTAL_MAX * D_MODEL];
__device__ __nv_bfloat16  g_ln2h[TOTAL_MAX * D_MODEL], g_ln2l[TOTAL_MAX * D_MODEL];
__device__ __nv_bfloat16  g_mffh[TOTAL_MAX * DFF],     g_mffl[TOTAL_MAX * DFF];
__device__ __nv_bfloat16  g_wqh [D_MODEL * DQKV],      g_wql [D_MODEL * DQKV];
__device__ __nv_bfloat16  g_woh [D_MODEL * D_MODEL],   g_wol [D_MODEL * D_MODEL];
__device__ __nv_bfloat16  g_w1h [D_MODEL * DFF],       g_w1l [D_MODEL * DFF];
__device__ __nv_bfloat16  g_w2h [DFF * D_MODEL],       g_w2l [DFF * D_MODEL];

__device__ __forceinline__ void split_store(__nv_bfloat16* hi, __nv_bfloat16* lo,
                                            size_t idx, float v) {
    __nv_bfloat16 h = __float2bfloat16(v);
    hi[idx] = h;
    lo[idx] = __float2bfloat16(v - __bfloat162float(h));
}

// ======================= weight transpose + split ===========================
// W[K,N] f32 -> Thi/Tlo [N,K] bf16 (K-major)
__global__ __launch_bounds__(256) void wsplit_kernel(
    const float* __restrict__ W, __nv_bfloat16* __restrict__ Thi,
    __nv_bfloat16* __restrict__ Tlo, int K, int N)
{
    __shared__ float tile[32][33];
    int n0 = blockIdx.x * 32, k0 = blockIdx.y * 32;
    int tx = threadIdx.x & 31, ty = threadIdx.x >> 5;
#pragma unroll
    for (int i = 0; i < 4; i++)
        tile[ty + i * 8][tx] = W[(size_t)(k0 + ty + i * 8) * N + n0 + tx];
    __syncthreads();
#pragma unroll
    for (int i = 0; i < 4; i++) {
        int n = ty + i * 8;
        float v = tile[tx][n];
        split_store(Thi, Tlo, (size_t)(n0 + n) * K + k0 + tx, v);
    }
}

// ======================= LayerNorm (writes bf16 hi/lo) ======================
__global__ __launch_bounds__(256) void ln_kernel(
    const float* __restrict__ x, const float* __restrict__ g,
    const float* __restrict__ beta,
    __nv_bfloat16* __restrict__ oh, __nv_bfloat16* __restrict__ ol)
{
    int row = blockIdx.x;
    const float* xr = x + (size_t)row * D_MODEL;
    float v[3];
    float s = 0.f;
#pragma unroll
    for (int i = 0; i < 3; i++) { v[i] = xr[threadIdx.x + i * 256]; s += v[i]; }

    __shared__ float red[8];
    __shared__ float stat[2];
#pragma unroll
    for (int o = 16; o; o >>= 1) s += __shfl_xor_sync(0xffffffffu, s, o);
    if ((threadIdx.x & 31) == 0) red[threadIdx.x >> 5] = s;
    __syncthreads();
    if (threadIdx.x < 8) {
        s = red[threadIdx.x];
#pragma unroll
        for (int o = 4; o; o >>= 1) s += __shfl_xor_sync(0xffu, s, o);
        if (threadIdx.x == 0) stat[0] = s * (1.f / (float)D_MODEL);
    }
    __syncthreads();
    float mu = stat[0];
    float s2 = 0.f;
#pragma unroll
    for (int i = 0; i < 3; i++) { float d0 = v[i] - mu; s2 += d0 * d0; }
#pragma unroll
    for (int o = 16; o; o >>= 1) s2 += __shfl_xor_sync(0xffffffffu, s2, o);
    __syncthreads();
    if ((threadIdx.x & 31) == 0) red[threadIdx.x >> 5] = s2;
    __syncthreads();
    if (threadIdx.x < 8) {
        s2 = red[threadIdx.x];
#pragma unroll
        for (int o = 4; o; o >>= 1) s2 += __shfl_xor_sync(0xffu, s2, o);
        if (threadIdx.x == 0) stat[1] = rsqrtf(s2 * (1.f / (float)D_MODEL) + 1e-6f);
    }
    __syncthreads();
    float rstd = stat[1];
#pragma unroll
    for (int i = 0; i < 3; i++) {
        int col = threadIdx.x + i * 256;
        float y = (v[i] - mu) * rstd * g[col] + beta[col];
        split_store(oh, ol, (size_t)row * D_MODEL + col, y);
    }
}

// ======================= mma.sync GEMM ======================================
// C[M,N] = A[M,K] @ W[K,N] via bf16 hi/lo 3-product split (AhBh + AhBl + AlBh).
// A: Ahi/Alo [M,K] K-major bf16. W: Bhi/Blo [N,K] K-major bf16 (pre-transposed).
// Block 128x128, BK=64 bf16 (128B rows, SW128 swizzle), 8 warps of 64x32.
// EPI: 0 = bias -> f32 C; 1 = bias + resid -> f32 C; 2 = bias + GELU -> bf16 hi/lo

#define TILE_BYTES 16384u                 // 128 rows x 128 bytes
#define BUF_BYTES  (4u * TILE_BYTES)      // Ah, Al, Bh, Bl
#define GEMM_SMEM  (2u * BUF_BYTES)       // 131072

template <bool GUARD>
__device__ __forceinline__ void stage_async(
    uint32_t dst, const __nv_bfloat16* __restrict__ src,
    int row0, int rmax, int K, int kpos, int t)
{
#pragma unroll
    for (int i = 0; i < 4; i++) {
        int q = t + i * 256;
        int r = q >> 3, c = q & 7;
        uint32_t off = (uint32_t)(r * 128 + c * 16);
        off ^= (off >> 3) & 0x70u;        // SW128 swizzle
        int rr = row0 + r;
        uint32_t sz = 16;
        if (GUARD && rr >= rmax) { rr = rmax - 1; sz = 0; }
        cp_async16(dst + off, src + (size_t)rr * K + kpos + c * 8, sz);
    }
}

template <int EPI>
__global__ __launch_bounds__(256, 1)
void mmagemm_kernel(const __nv_bfloat16* __restrict__ Ahi,
                    const __nv_bfloat16* __restrict__ Alo,
                    const __nv_bfloat16* __restrict__ Bhi,
                    const __nv_bfloat16* __restrict__ Blo,
                    const float* __restrict__ bias,
                    const float* __restrict__ resid,
                    float* __restrict__ C,
                    __nv_bfloat16* __restrict__ Chi,
                    __nv_bfloat16* __restrict__ Clo,
                    int M, int N, int K)
{
    extern __shared__ char smem[];
    uint32_t sb = smem_to_u32(smem);
    int t = threadIdx.x;
    int lid = t & 31, w = t >> 5;
    int wm = w >> 2, wn = w & 3;          // warp grid 2 x 4 -> warp tile 64 x 32
    int bm = blockIdx.y * 128, bn = blockIdx.x * 128;
    const int NK = K / 64;

    float acc[4][4][4];
#pragma unroll
    for (int mi = 0; mi < 4; mi++)
#pragma unroll
        for (int ni = 0; ni < 4; ni++)
#pragma unroll
            for (int j = 0; j < 4; j++) acc[mi][ni][j] = 0.f;

    // prologue: stage k-tile 0 into buffer 0
    stage_async<true >(sb + 0 * TILE_BYTES, Ahi, bm, M, K, 0, t);
    stage_async<true >(sb + 1 * TILE_BYTES, Alo, bm, M, K, 0, t);
    stage_async<false>(sb + 2 * TILE_BYTES, Bhi, bn, N, K, 0, t);
    stage_async<false>(sb + 3 * TILE_BYTES, Blo, bn, N, K, 0, t);
    CP_COMMIT();

    // lane-dependent ldmatrix address components
    int a_row_l = (lid & 7) + (((lid >> 3) & 1) << 3);   // A: bit3 -> +8 rows
    int a_kb_l  = ((lid >> 4) & 1) * 16;                 //    bit4 -> k high half
    int b_row_l = (lid & 7) + (((lid >> 4) & 1) << 3);   // B: bit4 -> +8 n-rows
    int b_kb_l  = ((lid >> 3) & 1) * 16;                 //    bit3 -> k high half

    for (int kt = 0; kt < NK; kt++) {
        if (kt + 1 < NK) {
            uint32_t nb = sb + (uint32_t)((kt + 1) & 1) * BUF_BYTES;
            int kp = (kt + 1) * 64;
            stage_async<true >(nb + 0 * TILE_BYTES, Ahi, bm, M, K, kp, t);
            stage_async<true >(nb + 1 * TILE_BYTES, Alo, bm, M, K, kp, t);
            stage_async<false>(nb + 2 * TILE_BYTES, Bhi, bn, N, K, kp, t);
            stage_async<false>(nb + 3 * TILE_BYTES, Blo, bn, N, K, kp, t);
            CP_COMMIT();
            CP_WAIT(1);
        } else {
            CP_WAIT(0);
        }
        __syncthreads();

        uint32_t base = sb + (uint32_t)(kt & 1) * BUF_BYTES;
#pragma unroll
        for (int kk = 0; kk < 4; kk++) {
            uint32_t ah[4][4], bh[4][2], bl[4][2];
#pragma unroll
            for (int mi = 0; mi < 4; mi++) {
                uint32_t off = (uint32_t)((wm * 64 + mi * 16 + a_row_l) * 128
                                          + kk * 32 + a_kb_l);
                off ^= (off >> 3) & 0x70u;
                ldsm4(ah[mi], base + 0 * TILE_BYTES + off);
            }
#pragma unroll
            for (int np = 0; np < 2; np++) {
                uint32_t off = (uint32_t)((wn * 32 + np * 16 + b_row_l) * 128
                                          + kk * 32 + b_kb_l);
                off ^= (off >> 3) & 0x70u;
                uint32_t r[4];
                ldsm4(r, base + 2 * TILE_BYTES + off);
                bh[np * 2][0] = r[0]; bh[np * 2][1] = r[1];
                bh[np * 2 + 1][0] = r[2]; bh[np * 2 + 1][1] = r[3];
                ldsm4(r, base + 3 * TILE_BYTES + off);
                bl[np * 2][0] = r[0]; bl[np * 2][1] = r[1];
                bl[np * 2 + 1][0] = r[2]; bl[np * 2 + 1][1] = r[3];
            }
#pragma unroll
            for (int mi = 0; mi < 4; mi++)
#pragma unroll
                for (int ni = 0; ni < 4; ni++)
                    mma16816(acc[mi][ni], ah[mi], bh[ni]);
#pragma unroll
            for (int mi = 0; mi < 4; mi++)
#pragma unroll
                for (int ni = 0; ni < 4; ni++)
                    mma16816(acc[mi][ni], ah[mi], bl[ni]);
#pragma unroll
            for (int mi = 0; mi < 4; mi++) {
                uint32_t al[4];
                uint32_t off = (uint32_t)((wm * 64 + mi * 16 + a_row_l) * 128
                                          + kk * 32 + a_kb_l);
                off ^= (off >> 3) & 0x70u;
                ldsm4(al, base + 1 * TILE_BYTES + off);
#pragma unroll
                for (int ni = 0; ni < 4; ni++)
                    mma16816(acc[mi][ni], al, bh[ni]);
            }
        }
        __syncthreads();
    }

    // ---------------- epilogue (register -> global) ----------------
#pragma unroll
    for (int mi = 0; mi < 4; mi++) {
        int r0 = bm + wm * 64 + mi * 16 + (lid >> 2);
#pragma unroll
        for (int half = 0; half < 2; half++) {
            int row = r0 + half * 8;
            if (row >= M) continue;
#pragma unroll
            for (int ni = 0; ni < 4; ni++) {
                int col = bn + wn * 32 + ni * 8 + (lid & 3) * 2;
                float v0 = acc[mi][ni][half * 2 + 0] + bias[col];
                float v1 = acc[mi][ni][half * 2 + 1] + bias[col + 1];
                if (EPI == 1) {
                    float2 rr = *(const float2*)(resid + (size_t)row * N + col);
                    v0 += rr.x; v1 += rr.y;
                }
                if (EPI == 2) {
                    v0 = 0.5f * v0 * (1.f + erff(v0 * 0.70710678118654752f));
                    v1 = 0.5f * v1 * (1.f + erff(v1 * 0.70710678118654752f));
                    split_store(Chi, Clo, (size_t)row * N + col, v0);
                    split_store(Chi, Clo, (size_t)row * N + col + 1, v1);
                } else {
                    *(float2*)(C + (size_t)row * N + col) = make_float2(v0, v1);
                }
            }
        }
    }
}

// ======================= ragged flash attention (fp32) ======================
__global__ __launch_bounds__(128) void attn_kernel(
    const float* __restrict__ qkv, const int* __restrict__ cu,
    __nv_bfloat16* __restrict__ oh, __nv_bfloat16* __restrict__ ol)
{
    int b = blockIdx.z, h = blockIdx.y, qt = blockIdx.x;
    int s0 = cu[b], s1 = cu[b + 1];
    int len = s1 - s0;
    int q0 = qt * 32;
    if (q0 >= len) return;
    int nq = min(32, len - q0);

    __shared__ float Qs[32][65];
    __shared__ float Ks[32][65];
    __shared__ float Vs[32][65];
    __shared__ float Ss[32][33];
    __shared__ float corr_s[32], ls_s[32];

    int t = threadIdx.x;
    int qi = t & 31;
    int kwarp = t >> 5;
    int oc = kwarp * 16;

    {
        int r = t >> 2, cbase = (t & 3) * 16;
        const float* qp = qkv + (size_t)(s0 + q0 + r) * DQKV + h * HDIM;
#pragma unroll
        for (int i = 0; i < 16; i++)
            Qs[r][cbase + i] = (r < nq) ? qp[cbase + i] : 0.f;
    }

    const float scale = 0.125f;
    float m = -1e30f, l = 0.f;
    float O[16];
#pragma unroll
    for (int i = 0; i < 16; i++) O[i] = 0.f;

    for (int k0 = 0; k0 < len; k0 += 32) {
        int nk = min(32, len - k0);
        {
            int r = t >> 2, cbase = (t & 3) * 16;
            const float* kp = qkv + (size_t)(s0 + k0 + r) * DQKV + h * HDIM + D_MODEL;
            if (r < nk) {
#pragma unroll
                for (int i = 0; i < 16; i++) {
                    Ks[r][cbase + i] = kp[cbase + i];
                    Vs[r][cbase + i] = kp[D_MODEL + cbase + i];
                }
            } else {
#pragma unroll
                for (int i = 0; i < 16; i++) {
                    Ks[r][cbase + i] = 0.f;
                    Vs[r][cbase + i] = 0.f;
                }
            }
        }
        __syncthreads();

        float sreg[8];
#pragma unroll
        for (int c = 0; c < 8; c++) sreg[c] = 0.f;
#pragma unroll 16
        for (int d = 0; d < 64; d++) {
            float rq = Qs[qi][d];
#pragma unroll
            for (int c = 0; c < 8; c++)
                sreg[c] += rq * Ks[kwarp * 8 + c][d];
        }
#pragma unroll
        for (int c = 0; c < 8; c++) {
            int kj = kwarp * 8 + c;
            Ss[qi][kj] = (kj < nk) ? sreg[c] * scale : -1e30f;
        }
        __syncthreads();

        if (t < 32) {
            float tm = m;
#pragma unroll
            for (int j = 0; j < 32; j++) tm = fmaxf(tm, Ss[t][j]);
            float corr = __expf(m - tm);
            float ssum = 0.f;
#pragma unroll
            for (int j = 0; j < 32; j++) {
                float p = __expf(Ss[t][j] - tm);
                Ss[t][j] = p;
                ssum += p;
            }
            l = l * corr + ssum;
            m = tm;
            corr_s[t] = corr;
        }
        __syncthreads();

        float corr = corr_s[qi];
#pragma unroll
        for (int i = 0; i < 16; i++) O[i] *= corr;
        for (int j = 0; j < nk; j++) {
            float p = Ss[qi][j];
#pragma unroll
            for (int i = 0; i < 16; i++)
                O[i] += p * Vs[j][oc + i];
        }
        __syncthreads();
    }

    if (t < 32) ls_s[t] = l;
    __syncthreads();
    float inv = 1.f / ls_s[qi];
    if (qi < nq) {
        size_t base = (size_t)(s0 + q0 + qi) * D_MODEL + h * HDIM + oc;
#pragma unroll
        for (int i = 0; i < 16; i++)
            split_store(oh, ol, base + i, O[i] * inv);
    }
}

// ======================= launch =============================================
extern "C" void kernel_launch(void* const* d_in, const int* in_sizes, int n_in,
                              void* d_out, int out_size)
{
    const float* x    = (const float*)d_in[0];
    const int*   cu   = (const int*)  d_in[1];
    const float* g1   = (const float*)d_in[2];
    const float* be1  = (const float*)d_in[3];
    const float* Wqkv = (const float*)d_in[4];
    const float* bqkv = (const float*)d_in[5];
    const float* Wo   = (const float*)d_in[6];
    const float* bo   = (const float*)d_in[7];
    const float* g2   = (const float*)d_in[8];
    const float* be2  = (const float*)d_in[9];
    const float* W1   = (const float*)d_in[10];
    const float* bf1  = (const float*)d_in[11];
    const float* W2   = (const float*)d_in[12];
    const float* bf2  = (const float*)d_in[13];
    float* out = (float*)d_out;

    int total = in_sizes[0] / D_MODEL;
    int nb    = in_sizes[1] - 1;

    float* qkv;
    __nv_bfloat16 *ln1h, *ln1l, *atth, *attl, *ln2h, *ln2l, *mffh, *mffl;
    __nv_bfloat16 *wqh, *wql, *woh, *wol, *w1h, *w1l, *w2h, *w2l;
    cudaGetSymbolAddress((void**)&qkv,  g_qkv);
    cudaGetSymbolAddress((void**)&ln1h, g_ln1h); cudaGetSymbolAddress((void**)&ln1l, g_ln1l);
    cudaGetSymbolAddress((void**)&atth, g_atth); cudaGetSymbolAddress((void**)&attl, g_attl);
    cudaGetSymbolAddress((void**)&ln2h, g_ln2h); cudaGetSymbolAddress((void**)&ln2l, g_ln2l);
    cudaGetSymbolAddress((void**)&mffh, g_mffh); cudaGetSymbolAddress((void**)&mffl, g_mffl);
    cudaGetSymbolAddress((void**)&wqh,  g_wqh);  cudaGetSymbolAddress((void**)&wql,  g_wql);
    cudaGetSymbolAddress((void**)&woh,  g_woh);  cudaGetSymbolAddress((void**)&wol,  g_wol);
    cudaGetSymbolAddress((void**)&w1h,  g_w1h);  cudaGetSymbolAddress((void**)&w1l,  g_w1l);
    cudaGetSymbolAddress((void**)&w2h,  g_w2h);  cudaGetSymbolAddress((void**)&w2l,  g_w2l);

    cudaFuncSetAttribute(mmagemm_kernel<0>, cudaFuncAttributeMaxDynamicSharedMemorySize, GEMM_SMEM);
    cudaFuncSetAttribute(mmagemm_kernel<1>, cudaFuncAttributeMaxDynamicSharedMemorySize, GEMM_SMEM);
    cudaFuncSetAttribute(mmagemm_kernel<2>, cudaFuncAttributeMaxDynamicSharedMemorySize, GEMM_SMEM);

    int mblk = (total + 127) / 128;

    // 0. weight transpose + hi/lo split
    wsplit_kernel<<<dim3(DQKV / 32,    D_MODEL / 32), 256>>>(Wqkv, wqh, wql, D_MODEL, DQKV);
    wsplit_kernel<<<dim3(D_MODEL / 32, D_MODEL / 32), 256>>>(Wo,   woh, wol, D_MODEL, D_MODEL);
    wsplit_kernel<<<dim3(DFF / 32,     D_MODEL / 32), 256>>>(W1,   w1h, w1l, D_MODEL, DFF);
    wsplit_kernel<<<dim3(D_MODEL / 32, DFF / 32),     256>>>(W2,   w2h, w2l, DFF, D_MODEL);

    // 1. LN1 -> hi/lo
    ln_kernel<<<total, 256>>>(x, g1, be1, ln1h, ln1l);
    // 2. QKV = LN1 @ Wqkv + bqkv  (f32 out)
    mmagemm_kernel<0><<<dim3(DQKV / 128, mblk), 256, GEMM_SMEM>>>(
        ln1h, ln1l, wqh, wql, bqkv, nullptr, qkv, nullptr, nullptr,
        total, DQKV, D_MODEL);
    // 3. ragged attention -> hi/lo
    attn_kernel<<<dim3(SMAX / 32, NHEAD, nb), 128>>>(qkv, cu, atth, attl);
    // 4. out = x + attn @ Wo + bo
    mmagemm_kernel<1><<<dim3(D_MODEL / 128, mblk), 256, GEMM_SMEM>>>(
        atth, attl, woh, wol, bo, x, out, nullptr, nullptr,
        total, D_MODEL, D_MODEL);
    // 5. LN2 -> hi/lo
    ln_kernel<<<total, 256>>>(out, g2, be2, ln2h, ln2l);
    // 6. mff = gelu(LN2 @ W1 + b_fc1) -> hi/lo
    mmagemm_kernel<2><<<dim3(DFF / 128, mblk), 256, GEMM_SMEM>>>(
        ln2h, ln2l, w1h, w1l, bf1, nullptr, nullptr, mffh, mffl,
        total, DFF, D_MODEL);
    // 7. out = out + mff @ W2 + b_fc2
    mmagemm_kernel<1><<<dim3(D_MODEL / 128, mblk), 256, GEMM_SMEM>>>(
        mffh, mffl, w2h, w2l, bf2, out, out, nullptr, nullptr,
        total, D_MODEL, DFF);
}

// round 14
// speedup vs baseline: 5.2021x; 1.9250x over previous
#include <cuda_runtime.h>
#include <cuda_bf16.h>
#include <math.h>
#include <stdint.h>

#define D_MODEL 768
#define NHEAD 12
#define HDIM 64
#define DQKV 2304
#define DFF 3072
#define TOTAL_MAX 8192
#define SMAX 1024

// ======================= PTX helpers (sm_80-compatible only) ================
__device__ __forceinline__ uint32_t smem_to_u32(const void* p) {
    uint32_t a;
    asm("{ .reg .u64 t; cvta.to.shared.u64 t, %1; cvt.u32.u64 %0, t; }"
        : "=r"(a) : "l"(p));
    return a;
}

__device__ __forceinline__ void cp_async16(uint32_t dst, const void* src, uint32_t sz) {
    asm volatile("cp.async.cg.shared.global [%0], [%1], 16, %2;"
                 :: "r"(dst), "l"(src), "r"(sz) : "memory");
}
#define CP_COMMIT()  asm volatile("cp.async.commit_group;" ::: "memory")
#define CP_WAIT(N)   asm volatile("cp.async.wait_group %0;" :: "n"(N) : "memory")

__device__ __forceinline__ void ldsm4(uint32_t* r, uint32_t addr) {
    asm volatile("ldmatrix.sync.aligned.m8n8.x4.shared.b16 {%0,%1,%2,%3}, [%4];"
                 : "=r"(r[0]), "=r"(r[1]), "=r"(r[2]), "=r"(r[3]) : "r"(addr));
}
__device__ __forceinline__ void ldsm4t(uint32_t* r, uint32_t addr) {
    asm volatile("ldmatrix.sync.aligned.m8n8.x4.trans.shared.b16 {%0,%1,%2,%3}, [%4];"
                 : "=r"(r[0]), "=r"(r[1]), "=r"(r[2]), "=r"(r[3]) : "r"(addr));
}

__device__ __forceinline__ void mma16816(float* d, const uint32_t* a, const uint32_t* b) {
    asm volatile(
        "mma.sync.aligned.m16n8k16.row.col.f32.bf16.bf16.f32 "
        "{%0,%1,%2,%3}, {%4,%5,%6,%7}, {%8,%9}, {%0,%1,%2,%3};"
        : "+f"(d[0]), "+f"(d[1]), "+f"(d[2]), "+f"(d[3])
        : "r"(a[0]), "r"(a[1]), "r"(a[2]), "r"(a[3]), "r"(b[0]), "r"(b[1]));
}

__device__ __forceinline__ uint32_t packbf(float lo, float hi) {
    __nv_bfloat16 l = __float2bfloat16(lo), h = __float2bfloat16(hi);
    return (uint32_t)__bfloat16_as_ushort(l) | ((uint32_t)__bfloat16_as_ushort(h) << 16);
}

// ======================= scratch (device globals) ===========================
__device__ __nv_bfloat16  g_qkvh[TOTAL_MAX * DQKV],    g_qkvl[TOTAL_MAX * DQKV];
__device__ __nv_bfloat16  g_ln1h[TOTAL_MAX * D_MODEL], g_ln1l[TOTAL_MAX * D_MODEL];
__device__ __nv_bfloat16  g_atth[TOTAL_MAX * D_MODEL], g_attl[TOTAL_MAX * D_MODEL];
__device__ __nv_bfloat16  g_ln2h[TOTAL_MAX * D_MODEL], g_ln2l[TOTAL_MAX * D_MODEL];
__device__ __nv_bfloat16  g_mffh[TOTAL_MAX * DFF],     g_mffl[TOTAL_MAX * DFF];
__device__ __nv_bfloat16  g_wqh [D_MODEL * DQKV],      g_wql [D_MODEL * DQKV];
__device__ __nv_bfloat16  g_woh [D_MODEL * D_MODEL],   g_wol [D_MODEL * D_MODEL];
__device__ __nv_bfloat16  g_w1h [D_MODEL * DFF],       g_w1l [D_MODEL * DFF];
__device__ __nv_bfloat16  g_w2h [DFF * D_MODEL],       g_w2l [DFF * D_MODEL];

__device__ __forceinline__ void split_store(__nv_bfloat16* hi, __nv_bfloat16* lo,
                                            size_t idx, float v) {
    __nv_bfloat16 h = __float2bfloat16(v);
    hi[idx] = h;
    lo[idx] = __float2bfloat16(v - __bfloat162float(h));
}

// ======================= weight transpose + split ===========================
__global__ __launch_bounds__(256) void wsplit_kernel(
    const float* __restrict__ W, __nv_bfloat16* __restrict__ Thi,
    __nv_bfloat16* __restrict__ Tlo, int K, int N)
{
    __shared__ float tile[32][33];
    int n0 = blockIdx.x * 32, k0 = blockIdx.y * 32;
    int tx = threadIdx.x & 31, ty = threadIdx.x >> 5;
#pragma unroll
    for (int i = 0; i < 4; i++)
        tile[ty + i * 8][tx] = W[(size_t)(k0 + ty + i * 8) * N + n0 + tx];
    __syncthreads();
#pragma unroll
    for (int i = 0; i < 4; i++) {
        int n = ty + i * 8;
        float v = tile[tx][n];
        split_store(Thi, Tlo, (size_t)(n0 + n) * K + k0 + tx, v);
    }
}

// ======================= LayerNorm (writes bf16 hi/lo) ======================
__global__ __launch_bounds__(256) void ln_kernel(
    const float* __restrict__ x, const float* __restrict__ g,
    const float* __restrict__ beta,
    __nv_bfloat16* __restrict__ oh, __nv_bfloat16* __restrict__ ol)
{
    int row = blockIdx.x;
    const float* xr = x + (size_t)row * D_MODEL;
    float v[3];
    float s = 0.f;
#pragma unroll
    for (int i = 0; i < 3; i++) { v[i] = xr[threadIdx.x + i * 256]; s += v[i]; }

    __shared__ float red[8];
    __shared__ float stat[2];
#pragma unroll
    for (int o = 16; o; o >>= 1) s += __shfl_xor_sync(0xffffffffu, s, o);
    if ((threadIdx.x & 31) == 0) red[threadIdx.x >> 5] = s;
    __syncthreads();
    if (threadIdx.x < 8) {
        s = red[threadIdx.x];
#pragma unroll
        for (int o = 4; o; o >>= 1) s += __shfl_xor_sync(0xffu, s, o);
        if (threadIdx.x == 0) stat[0] = s * (1.f / (float)D_MODEL);
    }
    __syncthreads();
    float mu = stat[0];
    float s2 = 0.f;
#pragma unroll
    for (int i = 0; i < 3; i++) { float d0 = v[i] - mu; s2 += d0 * d0; }
#pragma unroll
    for (int o = 16; o; o >>= 1) s2 += __shfl_xor_sync(0xffffffffu, s2, o);
    __syncthreads();
    if ((threadIdx.x & 31) == 0) red[threadIdx.x >> 5] = s2;
    __syncthreads();
    if (threadIdx.x < 8) {
        s2 = red[threadIdx.x];
#pragma unroll
        for (int o = 4; o; o >>= 1) s2 += __shfl_xor_sync(0xffu, s2, o);
        if (threadIdx.x == 0) stat[1] = rsqrtf(s2 * (1.f / (float)D_MODEL) + 1e-6f);
    }
    __syncthreads();
    float rstd = stat[1];
#pragma unroll
    for (int i = 0; i < 3; i++) {
        int col = threadIdx.x + i * 256;
        float y = (v[i] - mu) * rstd * g[col] + beta[col];
        split_store(oh, ol, (size_t)row * D_MODEL + col, y);
    }
}

// ======================= mma.sync GEMM ======================================
// EPI: 0 = bias -> bf16 hi/lo; 1 = bias + resid -> f32 C; 2 = bias + GELU -> bf16 hi/lo

#define TILE_BYTES 16384u
#define BUF_BYTES  (4u * TILE_BYTES)
#define GEMM_SMEM  (2u * BUF_BYTES)

template <bool GUARD>
__device__ __forceinline__ void stage_async(
    uint32_t dst, const __nv_bfloat16* __restrict__ src,
    int row0, int rmax, int K, int kpos, int t)
{
#pragma unroll
    for (int i = 0; i < 4; i++) {
        int q = t + i * 256;
        int r = q >> 3, c = q & 7;
        uint32_t off = (uint32_t)(r * 128 + c * 16);
        off ^= (off >> 3) & 0x70u;
        int rr = row0 + r;
        uint32_t sz = 16;
        if (GUARD && rr >= rmax) { rr = rmax - 1; sz = 0; }
        cp_async16(dst + off, src + (size_t)rr * K + kpos + c * 8, sz);
    }
}

template <int EPI>
__global__ __launch_bounds__(256, 1)
void mmagemm_kernel(const __nv_bfloat16* __restrict__ Ahi,
                    const __nv_bfloat16* __restrict__ Alo,
                    const __nv_bfloat16* __restrict__ Bhi,
                    const __nv_bfloat16* __restrict__ Blo,
                    const float* __restrict__ bias,
                    const float* __restrict__ resid,
                    float* __restrict__ C,
                    __nv_bfloat16* __restrict__ Chi,
                    __nv_bfloat16* __restrict__ Clo,
                    int M, int N, int K)
{
    extern __shared__ char smem[];
    uint32_t sb = smem_to_u32(smem);
    int t = threadIdx.x;
    int lid = t & 31, w = t >> 5;
    int wm = w >> 2, wn = w & 3;
    int bm = blockIdx.y * 128, bn = blockIdx.x * 128;
    const int NK = K / 64;

    float acc[4][4][4];
#pragma unroll
    for (int mi = 0; mi < 4; mi++)
#pragma unroll
        for (int ni = 0; ni < 4; ni++)
#pragma unroll
            for (int j = 0; j < 4; j++) acc[mi][ni][j] = 0.f;

    stage_async<true >(sb + 0 * TILE_BYTES, Ahi, bm, M, K, 0, t);
    stage_async<true >(sb + 1 * TILE_BYTES, Alo, bm, M, K, 0, t);
    stage_async<false>(sb + 2 * TILE_BYTES, Bhi, bn, N, K, 0, t);
    stage_async<false>(sb + 3 * TILE_BYTES, Blo, bn, N, K, 0, t);
    CP_COMMIT();

    int a_row_l = (lid & 7) + (((lid >> 3) & 1) << 3);
    int a_kb_l  = ((lid >> 4) & 1) * 16;
    int b_row_l = (lid & 7) + (((lid >> 4) & 1) << 3);
    int b_kb_l  = ((lid >> 3) & 1) * 16;

    for (int kt = 0; kt < NK; kt++) {
        if (kt + 1 < NK) {
            uint32_t nb = sb + (uint32_t)((kt + 1) & 1) * BUF_BYTES;
            int kp = (kt + 1) * 64;
            stage_async<true >(nb + 0 * TILE_BYTES, Ahi, bm, M, K, kp, t);
            stage_async<true >(nb + 1 * TILE_BYTES, Alo, bm, M, K, kp, t);
            stage_async<false>(nb + 2 * TILE_BYTES, Bhi, bn, N, K, kp, t);
            stage_async<false>(nb + 3 * TILE_BYTES, Blo, bn, N, K, kp, t);
            CP_COMMIT();
            CP_WAIT(1);
        } else {
            CP_WAIT(0);
        }
        __syncthreads();

        uint32_t base = sb + (uint32_t)(kt & 1) * BUF_BYTES;
#pragma unroll
        for (int kk = 0; kk < 4; kk++) {
            uint32_t ah[4][4], bh[4][2], bl[4][2];
#pragma unroll
            for (int mi = 0; mi < 4; mi++) {
                uint32_t off = (uint32_t)((wm * 64 + mi * 16 + a_row_l) * 128
                                          + kk * 32 + a_kb_l);
                off ^= (off >> 3) & 0x70u;
                ldsm4(ah[mi], base + 0 * TILE_BYTES + off);
            }
#pragma unroll
            for (int np = 0; np < 2; np++) {
                uint32_t off = (uint32_t)((wn * 32 + np * 16 + b_row_l) * 128
                                          + kk * 32 + b_kb_l);
                off ^= (off >> 3) & 0x70u;
                uint32_t r[4];
                ldsm4(r, base + 2 * TILE_BYTES + off);
                bh[np * 2][0] = r[0]; bh[np * 2][1] = r[1];
                bh[np * 2 + 1][0] = r[2]; bh[np * 2 + 1][1] = r[3];
                ldsm4(r, base + 3 * TILE_BYTES + off);
                bl[np * 2][0] = r[0]; bl[np * 2][1] = r[1];
                bl[np * 2 + 1][0] = r[2]; bl[np * 2 + 1][1] = r[3];
            }
#pragma unroll
            for (int mi = 0; mi < 4; mi++)
#pragma unroll
                for (int ni = 0; ni < 4; ni++)
                    mma16816(acc[mi][ni], ah[mi], bh[ni]);
#pragma unroll
            for (int mi = 0; mi < 4; mi++)
#pragma unroll
                for (int ni = 0; ni < 4; ni++)
                    mma16816(acc[mi][ni], ah[mi], bl[ni]);
#pragma unroll
            for (int mi = 0; mi < 4; mi++) {
                uint32_t al[4];
                uint32_t off = (uint32_t)((wm * 64 + mi * 16 + a_row_l) * 128
                                          + kk * 32 + a_kb_l);
                off ^= (off >> 3) & 0x70u;
                ldsm4(al, base + 1 * TILE_BYTES + off);
#pragma unroll
                for (int ni = 0; ni < 4; ni++)
                    mma16816(acc[mi][ni], al, bh[ni]);
            }
        }
        __syncthreads();
    }

#pragma unroll
    for (int mi = 0; mi < 4; mi++) {
        int r0 = bm + wm * 64 + mi * 16 + (lid >> 2);
#pragma unroll
        for (int half = 0; half < 2; half++) {
            int row = r0 + half * 8;
            if (row >= M) continue;
#pragma unroll
            for (int ni = 0; ni < 4; ni++) {
                int col = bn + wn * 32 + ni * 8 + (lid & 3) * 2;
                float v0 = acc[mi][ni][half * 2 + 0] + bias[col];
                float v1 = acc[mi][ni][half * 2 + 1] + bias[col + 1];
                if (EPI == 1) {
                    float2 rr = *(const float2*)(resid + (size_t)row * N + col);
                    v0 += rr.x; v1 += rr.y;
                    *(float2*)(C + (size_t)row * N + col) = make_float2(v0, v1);
                } else if (EPI == 2) {
                    v0 = 0.5f * v0 * (1.f + erff(v0 * 0.70710678118654752f));
                    v1 = 0.5f * v1 * (1.f + erff(v1 * 0.70710678118654752f));
                    split_store(Chi, Clo, (size_t)row * N + col, v0);
                    split_store(Chi, Clo, (size_t)row * N + col + 1, v1);
                } else {
                    split_store(Chi, Clo, (size_t)row * N + col, v0);
                    split_store(Chi, Clo, (size_t)row * N + col + 1, v1);
                }
            }
        }
    }
}

// ======================= tensor-core flash attention ========================
// block: 64 queries x 1 head, 128 threads (4 warps x m16). K-tiles of 64.
// Q,K,V from qkv hi/lo bf16 [token][2304]. Output hi/lo bf16 [token][768].

#define AQH 0u
#define AQL 8192u
#define AKV(buf) (16384u + (uint32_t)(buf) * 32768u)
#define ATT_SMEM 81920

__device__ __forceinline__ void stage_attn(
    uint32_t dst, const __nv_bfloat16* __restrict__ src,
    int tok0, int nvalid, int colbase, int t)
{
#pragma unroll
    for (int i = 0; i < 4; i++) {
        int idx = t + i * 128;
        int r = idx >> 3, c = idx & 7;
        uint32_t off = (uint32_t)(r * 128 + c * 16);
        off ^= (off >> 3) & 0x70u;
        int rr = min(r, nvalid - 1);
        uint32_t sz = (r < nvalid) ? 16u : 0u;
        cp_async16(dst + off, src + (size_t)(tok0 + rr) * DQKV + colbase + c * 8, sz);
    }
}

__global__ __launch_bounds__(128, 2) void attn_mma_kernel(
    const __nv_bfloat16* __restrict__ qh, const __nv_bfloat16* __restrict__ ql,
    const int* __restrict__ cu,
    __nv_bfloat16* __restrict__ oh, __nv_bfloat16* __restrict__ ol)
{
    extern __shared__ char sm[];
    uint32_t sb = smem_to_u32(sm);
    int b = blockIdx.z, h = blockIdx.y, qt = blockIdx.x;
    int s0 = cu[b];
    int len = cu[b + 1] - s0;
    int q0 = qt * 64;
    if (q0 >= len) return;
    int nq = min(64, len - q0);
    int t = threadIdx.x, lid = t & 31, w = t >> 5;

    // stage Q hi/lo + KV tile 0
    stage_attn(sb + AQH, qh, s0 + q0, nq, h * HDIM, t);
    stage_attn(sb + AQL, ql, s0 + q0, nq, h * HDIM, t);
    {
        int nv = min(64, len);
        stage_attn(sb + AKV(0) + 0,     qh, s0, nv, 768 + h * HDIM, t);
        stage_attn(sb + AKV(0) + 8192,  ql, s0, nv, 768 + h * HDIM, t);
        stage_attn(sb + AKV(0) + 16384, qh, s0, nv, 1536 + h * HDIM, t);
        stage_attn(sb + AKV(0) + 24576, ql, s0, nv, 1536 + h * HDIM, t);
    }
    CP_COMMIT();

    int a_row = (lid & 7) + (((lid >> 3) & 1) << 3);
    int a_kb  = ((lid >> 4) & 1) * 16;
    int b_row = (lid & 7) + (((lid >> 4) & 1) << 3);
    int b_kb  = ((lid >> 3) & 1) * 16;
    int v_row = (lid & 7) + (((lid >> 3) & 1) << 3);   // V (trans): bit3 -> +8 k rows
    int v_cb  = ((lid >> 4) & 1) * 16;                 //            bit4 -> +16B n cols

    float m0 = -1e30f, m1 = -1e30f, l0 = 0.f, l1 = 0.f;
    float o[8][4];
#pragma unroll
    for (int nt = 0; nt < 8; nt++)
#pragma unroll
        for (int j = 0; j < 4; j++) o[nt][j] = 0.f;

    int ntk = (len + 63) >> 6;
    for (int kt = 0; kt < ntk; kt++) {
        if (kt + 1 < ntk) {
            uint32_t nb = sb + AKV((kt + 1) & 1);
            int k1 = (kt + 1) * 64;
            int nv = min(64, len - k1);
            stage_attn(nb + 0,     qh, s0 + k1, nv, 768 + h * HDIM, t);
            stage_attn(nb + 8192,  ql, s0 + k1, nv, 768 + h * HDIM, t);
            stage_attn(nb + 16384, qh, s0 + k1, nv, 1536 + h * HDIM, t);
            stage_attn(nb + 24576, ql, s0 + k1, nv, 1536 + h * HDIM, t);
            CP_COMMIT();
            CP_WAIT(1);
        } else {
            CP_WAIT(0);
        }
        __syncthreads();

        uint32_t kb = sb + AKV(kt & 1);

        // ---- S = scale * (Qh Kh + Qh Kl + Ql Kh) ----
        float s[8][4];
#pragma unroll
        for (int nt = 0; nt < 8; nt++)
#pragma unroll
            for (int j = 0; j < 4; j++) s[nt][j] = 0.f;

#pragma unroll
        for (int kc = 0; kc < 4; kc++) {
            uint32_t offa = (uint32_t)((w * 16 + a_row) * 128 + kc * 32 + a_kb);
            offa ^= (offa >> 3) & 0x70u;
            uint32_t ah[4], al[4];
            ldsm4(ah, sb + AQH + offa);
            ldsm4(al, sb + AQL + offa);
#pragma unroll
            for (int np = 0; np < 4; np++) {
                uint32_t offb = (uint32_t)((np * 16 + b_row) * 128 + kc * 32 + b_kb);
                offb ^= (offb >> 3) & 0x70u;
                uint32_t rh[4], rl[4];
                ldsm4(rh, kb + 0 + offb);
                ldsm4(rl, kb + 8192 + offb);
                uint32_t bh0[2] = {rh[0], rh[1]}, bh1[2] = {rh[2], rh[3]};
                uint32_t bl0[2] = {rl[0], rl[1]}, bl1[2] = {rl[2], rl[3]};
                mma16816(s[np * 2],     ah, bh0);
                mma16816(s[np * 2],     ah, bl0);
                mma16816(s[np * 2],     al, bh0);
                mma16816(s[np * 2 + 1], ah, bh1);
                mma16816(s[np * 2 + 1], ah, bl1);
                mma16816(s[np * 2 + 1], al, bh1);
            }
        }

        // ---- mask + online softmax (thread rows: g = w*16+(lid>>2), g+8) ----
        float mn0 = m0, mn1 = m1;
#pragma unroll
        for (int nt = 0; nt < 8; nt++) {
            int c0 = kt * 64 + nt * 8 + (lid & 3) * 2;
            bool v0 = c0 < len, v1 = (c0 + 1) < len;
            s[nt][0] = v0 ? s[nt][0] * 0.125f : -1e30f;
            s[nt][1] = v1 ? s[nt][1] * 0.125f : -1e30f;
            s[nt][2] = v0 ? s[nt][2] * 0.125f : -1e30f;
            s[nt][3] = v1 ? s[nt][3] * 0.125f : -1e30f;
            mn0 = fmaxf(mn0, fmaxf(s[nt][0], s[nt][1]));
            mn1 = fmaxf(mn1, fmaxf(s[nt][2], s[nt][3]));
        }
        mn0 = fmaxf(mn0, __shfl_xor_sync(0xffffffffu, mn0, 1));
        mn0 = fmaxf(mn0, __shfl_xor_sync(0xffffffffu, mn0, 2));
        mn1 = fmaxf(mn1, __shfl_xor_sync(0xffffffffu, mn1, 1));
        mn1 = fmaxf(mn1, __shfl_xor_sync(0xffffffffu, mn1, 2));
        float corr0 = __expf(m0 - mn0), corr1 = __expf(m1 - mn1);
        m0 = mn0; m1 = mn1;
        float sum0 = 0.f, sum1 = 0.f;
#pragma unroll
        for (int nt = 0; nt < 8; nt++) {
            s[nt][0] = __expf(s[nt][0] - m0);
            s[nt][1] = __expf(s[nt][1] - m0);
            s[nt][2] = __expf(s[nt][2] - m1);
            s[nt][3] = __expf(s[nt][3] - m1);
            sum0 += s[nt][0] + s[nt][1];
            sum1 += s[nt][2] + s[nt][3];
        }
        sum0 += __shfl_xor_sync(0xffffffffu, sum0, 1);
        sum0 += __shfl_xor_sync(0xffffffffu, sum0, 2);
        sum1 += __shfl_xor_sync(0xffffffffu, sum1, 1);
        sum1 += __shfl_xor_sync(0xffffffffu, sum1, 2);
        l0 = l0 * corr0 + sum0;
        l1 = l1 * corr1 + sum1;
#pragma unroll
        for (int nt = 0; nt < 8; nt++) {
            o[nt][0] *= corr0; o[nt][1] *= corr0;
            o[nt][2] *= corr1; o[nt][3] *= corr1;
        }

        // ---- O += (Ph Vh + Ph Vl + Pl Vh) ----
#pragma unroll
        for (int kc = 0; kc < 4; kc++) {
            // P A-frags from S fragments (n-tiles 2kc, 2kc+1 -> k 0-7, 8-15)
            uint32_t aph[4], apl[4];
            {
                float p00 = s[2 * kc][0],     p01 = s[2 * kc][1];
                float p10 = s[2 * kc][2],     p11 = s[2 * kc][3];
                float p20 = s[2 * kc + 1][0], p21 = s[2 * kc + 1][1];
                float p30 = s[2 * kc + 1][2], p31 = s[2 * kc + 1][3];
                __nv_bfloat16 h00 = __float2bfloat16(p00), h01 = __float2bfloat16(p01);
                __nv_bfloat16 h10 = __float2bfloat16(p10), h11 = __float2bfloat16(p11);
                __nv_bfloat16 h20 = __float2bfloat16(p20), h21 = __float2bfloat16(p21);
                __nv_bfloat16 h30 = __float2bfloat16(p30), h31 = __float2bfloat16(p31);
                aph[0] = (uint32_t)__bfloat16_as_ushort(h00) | ((uint32_t)__bfloat16_as_ushort(h01) << 16);
                aph[1] = (uint32_t)__bfloat16_as_ushort(h10) | ((uint32_t)__bfloat16_as_ushort(h11) << 16);
                aph[2] = (uint32_t)__bfloat16_as_ushort(h20) | ((uint32_t)__bfloat16_as_ushort(h21) << 16);
                aph[3] = (uint32_t)__bfloat16_as_ushort(h30) | ((uint32_t)__bfloat16_as_ushort(h31) << 16);
                apl[0] = packbf(p00 - __bfloat162float(h00), p01 - __bfloat162float(h01));
                apl[1] = packbf(p10 - __bfloat162float(h10), p11 - __bfloat162float(h11));
                apl[2] = packbf(p20 - __bfloat162float(h20), p21 - __bfloat162float(h21));
                apl[3] = packbf(p30 - __bfloat162float(h30), p31 - __bfloat162float(h31));
            }
#pragma unroll
            for (int np = 0; np < 4; np++) {
                uint32_t offv = (uint32_t)((kc * 16 + v_row) * 128 + np * 32 + v_cb);
                offv ^= (offv >> 3) & 0x70u;
                uint32_t rh[4], rl[4];
                ldsm4t(rh, kb + 16384 + offv);
                ldsm4t(rl, kb + 24576 + offv);
                uint32_t bh0[2] = {rh[0], rh[1]}, bh1[2] = {rh[2], rh[3]};
                uint32_t bl0[2] = {rl[0], rl[1]}, bl1[2] = {rl[2], rl[3]};
                mma16816(o[np * 2],     aph, bh0);
                mma16816(o[np * 2],     aph, bl0);
                mma16816(o[np * 2],     apl, bh0);
                mma16816(o[np * 2 + 1], aph, bh1);
                mma16816(o[np * 2 + 1], aph, bl1);
                mma16816(o[np * 2 + 1], apl, bh1);
            }
        }
        __syncthreads();
    }

    // ---- epilogue ----
    int r0 = w * 16 + (lid >> 2);
    float inv0 = 1.f / l0, inv1 = 1.f / l1;
#pragma unroll
    for (int nt = 0; nt < 8; nt++) {
        int col = h * HDIM + nt * 8 + (lid & 3) * 2;
        if (r0 < nq) {
            size_t base = (size_t)(s0 + q0 + r0) * D_MODEL + col;
            split_store(oh, ol, base,     o[nt][0] * inv0);
            split_store(oh, ol, base + 1, o[nt][1] * inv0);
        }
        if (r0 + 8 < nq) {
            size_t base = (size_t)(s0 + q0 + r0 + 8) * D_MODEL + col;
            split_store(oh, ol, base,     o[nt][2] * inv1);
            split_store(oh, ol, base + 1, o[nt][3] * inv1);
        }
    }
}

// ======================= launch =============================================
extern "C" void kernel_launch(void* const* d_in, const int* in_sizes, int n_in,
                              void* d_out, int out_size)
{
    const float* x    = (const float*)d_in[0];
    const int*   cu   = (const int*)  d_in[1];
    const float* g1   = (const float*)d_in[2];
    const float* be1  = (const float*)d_in[3];
    const float* Wqkv = (const float*)d_in[4];
    const float* bqkv = (const float*)d_in[5];
    const float* Wo   = (const float*)d_in[6];
    const float* bo   = (const float*)d_in[7];
    const float* g2   = (const float*)d_in[8];
    const float* be2  = (const float*)d_in[9];
    const float* W1   = (const float*)d_in[10];
    const float* bf1  = (const float*)d_in[11];
    const float* W2   = (const float*)d_in[12];
    const float* bf2  = (const float*)d_in[13];
    float* out = (float*)d_out;

    int total = in_sizes[0] / D_MODEL;
    int nb    = in_sizes[1] - 1;

    __nv_bfloat16 *qkvh, *qkvl;
    __nv_bfloat16 *ln1h, *ln1l, *atth, *attl, *ln2h, *ln2l, *mffh, *mffl;
    __nv_bfloat16 *wqh, *wql, *woh, *wol, *w1h, *w1l, *w2h, *w2l;
    cudaGetSymbolAddress((void**)&qkvh, g_qkvh); cudaGetSymbolAddress((void**)&qkvl, g_qkvl);
    cudaGetSymbolAddress((void**)&ln1h, g_ln1h); cudaGetSymbolAddress((void**)&ln1l, g_ln1l);
    cudaGetSymbolAddress((void**)&atth, g_atth); cudaGetSymbolAddress((void**)&attl, g_attl);
    cudaGetSymbolAddress((void**)&ln2h, g_ln2h); cudaGetSymbolAddress((void**)&ln2l, g_ln2l);
    cudaGetSymbolAddress((void**)&mffh, g_mffh); cudaGetSymbolAddress((void**)&mffl, g_mffl);
    cudaGetSymbolAddress((void**)&wqh,  g_wqh);  cudaGetSymbolAddress((void**)&wql,  g_wql);
    cudaGetSymbolAddress((void**)&woh,  g_woh);  cudaGetSymbolAddress((void**)&wol,  g_wol);
    cudaGetSymbolAddress((void**)&w1h,  g_w1h);  cudaGetSymbolAddress((void**)&w1l,  g_w1l);
    cudaGetSymbolAddress((void**)&w2h,  g_w2h);  cudaGetSymbolAddress((void**)&w2l,  g_w2l);

    cudaFuncSetAttribute(mmagemm_kernel<0>, cudaFuncAttributeMaxDynamicSharedMemorySize, GEMM_SMEM);
    cudaFuncSetAttribute(mmagemm_kernel<1>, cudaFuncAttributeMaxDynamicSharedMemorySize, GEMM_SMEM);
    cudaFuncSetAttribute(mmagemm_kernel<2>, cudaFuncAttributeMaxDynamicSharedMemorySize, GEMM_SMEM);
    cudaFuncSetAttribute(attn_mma_kernel,   cudaFuncAttributeMaxDynamicSharedMemorySize, ATT_SMEM);

    int mblk = (total + 127) / 128;

    // 0. weight transpose + hi/lo split
    wsplit_kernel<<<dim3(DQKV / 32,    D_MODEL / 32), 256>>>(Wqkv, wqh, wql, D_MODEL, DQKV);
    wsplit_kernel<<<dim3(D_MODEL / 32, D_MODEL / 32), 256>>>(Wo,   woh, wol, D_MODEL, D_MODEL);
    wsplit_kernel<<<dim3(DFF / 32,     D_MODEL / 32), 256>>>(W1,   w1h, w1l, D_MODEL, DFF);
    wsplit_kernel<<<dim3(D_MODEL / 32, DFF / 32),     256>>>(W2,   w2h, w2l, DFF, D_MODEL);

    // 1. LN1 -> hi/lo
    ln_kernel<<<total, 256>>>(x, g1, be1, ln1h, ln1l);
    // 2. QKV = LN1 @ Wqkv + bqkv  -> bf16 hi/lo
    mmagemm_kernel<0><<<dim3(DQKV / 128, mblk), 256, GEMM_SMEM>>>(
        ln1h, ln1l, wqh, wql, bqkv, nullptr, nullptr, qkvh, qkvl,
        total, DQKV, D_MODEL);
    // 3. ragged flash attention (tensor cores) -> hi/lo
    attn_mma_kernel<<<dim3(SMAX / 64, NHEAD, nb), 128, ATT_SMEM>>>(
        qkvh, qkvl, cu, atth, attl);
    // 4. out = x + attn @ Wo + bo
    mmagemm_kernel<1><<<dim3(D_MODEL / 128, mblk), 256, GEMM_SMEM>>>(
        atth, attl, woh, wol, bo, x, out, nullptr, nullptr,
        total, D_MODEL, D_MODEL);
    // 5. LN2 -> hi/lo
    ln_kernel<<<total, 256>>>(out, g2, be2, ln2h, ln2l);
    // 6. mff = gelu(LN2 @ W1 + b_fc1) -> hi/lo
    mmagemm_kernel<2><<<dim3(DFF / 128, mblk), 256, GEMM_SMEM>>>(
        ln2h, ln2l, w1h, w1l, bf1, nullptr, nullptr, mffh, mffl,
        total, DFF, D_MODEL);
    // 7. out = out + mff @ W2 + b_fc2
    mmagemm_kernel<1><<<dim3(D_MODEL / 128, mblk), 256, GEMM_SMEM>>>(
        mffh, mffl, w2h, w2l, bf2, out, out, nullptr, nullptr,
        total, D_MODEL, DFF);
}